// round 14
// baseline (speedup 1.0000x reference)
#include <cuda_runtime.h>
#include <cuda_fp16.h>
#include <cuda_bf16.h>

#define BATCH   2
#define CH      256
#define FH      96
#define FW      96
#define FHW     (FH * FW)
#define POOLED  7
#define NBINS   (POOLED * POOLED)
#define N_ROIS  512
#define SPATIAL_SCALE 0.0625f
#define TRANS_STD     0.1f

#define CH_HALF 128
#define ROW_BYTES_H (FW * CH * 2)
#define COL_BYTES_H (CH * 2)

// NHWC fp16 scratch copy of the feature map: 9.4 MB (L2-resident)
__device__ __align__(128) __half g_feat_h[BATCH * FHW * CH];

__device__ __forceinline__ __half2 u2h(unsigned int u) { return *(__half2*)&u; }
__device__ __forceinline__ unsigned int h2u(__half2 h) { return *(unsigned int*)&h; }

// Guaranteed single LDG.64 (ptxas cannot split a v2 asm load).
__device__ __forceinline__ uint2 ldg64cs(const void* p) {
    uint2 v;
    asm("ld.global.nc.v2.u32 {%0, %1}, [%2];" : "=r"(v.x), "=r"(v.y) : "l"(p));
    return v;
}

// ---------------------------------------------------------------------------
// Transpose NCHW f32 -> NHWC f16 via 32x32 shared tiles.
// ---------------------------------------------------------------------------
__global__ __launch_bounds__(256) void nchw_to_nhwc_half_kernel(const float* __restrict__ in) {
    __shared__ float tile[32][33];
    const int b   = blockIdx.z;
    const int hw0 = blockIdx.x * 32;
    const int c0  = blockIdx.y * 32;

    const float* src = in + (size_t)b * CH * FHW;
    #pragma unroll
    for (int j = 0; j < 32; j += 8) {
        tile[threadIdx.y + j][threadIdx.x] =
            src[(size_t)(c0 + threadIdx.y + j) * FHW + hw0 + threadIdx.x];
    }
    __syncthreads();

    const int lane = threadIdx.y * 32 + threadIdx.x;
    const int cp   = lane & 15;
    const int hr   = lane >> 4;
    __half2* dst2 = (__half2*)g_feat_h + (size_t)b * FHW * (CH / 2);
    #pragma unroll
    for (int s = 0; s < 2; s++) {
        const int hl = hr + s * 16;
        const float a  = tile[2 * cp][hl];
        const float bv = tile[2 * cp + 1][hl];
        dst2[(size_t)(hw0 + hl) * (CH / 2) + (c0 >> 1) + cp] = __floats2half2_rn(a, bv);
    }
}

// ---------------------------------------------------------------------------
// Deformable PS-RoI pooling, v14 = v13 with 6 CTAs/SM (occupancy bump now
// that issue is no longer the ceiling).
// Grid (4, 512): blockIdx.x = half*2 + binhalf. 256 threads, warp = bin.
// ---------------------------------------------------------------------------

template <int NB>
__device__ __forceinline__ void store_tile(float* __restrict__ o,
                                           const float* __restrict__ s_outf,
                                           int tid)
{
    #pragma unroll 4
    for (int i = tid; i < CH_HALF * NB; i += 256) {
        const int c = i / NB;
        const int j = i - c * NB;
        o[c * NBINS + j] = s_outf[j * 132 + c];
    }
}

__global__ __launch_bounds__(256, 6) void dpsroi_pool_kernel(
    const float* __restrict__ rois,     // [N_ROIS, 5]
    const float* __restrict__ trans,    // [N_ROIS, 2, 7, 7]
    float* __restrict__ out)            // [N_ROIS, CH, 7, 7]
{
    __shared__ float4 s_out4[25 * 33];        // [bin][33 float4] = 13.2 KB
    __shared__ int4   s_row[25];              // 4 row byte-offsets per bin
    __shared__ int4   s_col[25];              // 4 col byte-offsets per bin
    __shared__ uint4  s_axh[25];              // 4 half2-broadcast x weights
    __shared__ float4 s_ay[25];               // y weights * inv(count)

    const int half = blockIdx.x >> 1;
    const int bh   = blockIdx.x & 1;          // 0 -> bins 0..23, 1 -> 24..48
    const int n    = blockIdx.y;
    const int tid  = threadIdx.x;
    const int cg   = tid & 31;
    const int bsub = tid >> 5;
    const int nb   = 24 + bh;
    const int bin0 = bh * 24;

    const float* roi = rois + n * 5;
    const int   bidx = (int)roi[0];

    // ---------------- Phase 1: per-bin tables ----------------
    if (tid < nb) {
        const float x1 = rintf(roi[1]) * SPATIAL_SCALE - 0.5f;
        const float y1 = rintf(roi[2]) * SPATIAL_SCALE - 0.5f;
        const float x2 = (rintf(roi[3]) + 1.0f) * SPATIAL_SCALE - 0.5f;
        const float y2 = (rintf(roi[4]) + 1.0f) * SPATIAL_SCALE - 0.5f;
        const float rw = fmaxf(x2 - x1, 0.1f);
        const float rh = fmaxf(y2 - y1, 0.1f);
        const float bin_w = rw * (1.0f / POOLED);
        const float bin_h = rh * (1.0f / POOLED);
        const float sub_w = bin_w * 0.5f;
        const float sub_h = bin_h * 0.5f;

        const int bin = bin0 + tid;
        const int ph = bin / POOLED;
        const int pw = bin % POOLED;

        const float tx = __ldg(trans + (size_t)n * 2 * NBINS + bin) * TRANS_STD;
        const float ty = __ldg(trans + (size_t)n * 2 * NBINS + NBINS + bin) * TRANS_STD;

        const float wstart = (float)pw * bin_w + x1 + tx * rw;
        const float hstart = (float)ph * bin_h + y1 + ty * rh;

        const float w0 = wstart, w1 = wstart + sub_w;
        const float h0 = hstart, h1 = hstart + sub_h;

        const float vx0 = (w0 >= -0.5f && w0 <= (float)FW - 0.5f) ? 1.0f : 0.0f;
        const float vx1 = (w1 >= -0.5f && w1 <= (float)FW - 0.5f) ? 1.0f : 0.0f;
        const float vy0 = (h0 >= -0.5f && h0 <= (float)FH - 0.5f) ? 1.0f : 0.0f;
        const float vy1 = (h1 >= -0.5f && h1 <= (float)FH - 0.5f) ? 1.0f : 0.0f;

        const float wc0 = fminf(fmaxf(w0, 0.0f), (float)FW - 1.0f);
        const float wc1 = fminf(fmaxf(w1, 0.0f), (float)FW - 1.0f);
        const float hc0 = fminf(fmaxf(h0, 0.0f), (float)FH - 1.0f);
        const float hc1 = fminf(fmaxf(h1, 0.0f), (float)FH - 1.0f);

        const float fx0 = floorf(wc0), fx1 = floorf(wc1);
        const float fy0 = floorf(hc0), fy1 = floorf(hc1);
        const float dx0 = wc0 - fx0, dx1 = wc1 - fx1;
        const float dy0 = hc0 - fy0, dy1 = hc1 - fy1;

        int4 col, row;
        col.x = (int)fx0 * COL_BYTES_H;
        col.y = (int)ceilf(wc0) * COL_BYTES_H;
        col.z = (int)fx1 * COL_BYTES_H;
        col.w = (int)ceilf(wc1) * COL_BYTES_H;
        row.x = (int)fy0 * ROW_BYTES_H;
        row.y = (int)ceilf(hc0) * ROW_BYTES_H;
        row.z = (int)fy1 * ROW_BYTES_H;
        row.w = (int)ceilf(hc1) * ROW_BYTES_H;

        const float count = (vx0 + vx1) * (vy0 + vy1);
        const float inv = (count > 0.0f) ? (1.0f / count) : 0.0f;

        uint4 axh;
        axh.x = h2u(__float2half2_rn(vx0 * (1.0f - dx0)));
        axh.y = h2u(__float2half2_rn(vx0 * dx0));
        axh.z = h2u(__float2half2_rn(vx1 * (1.0f - dx1)));
        axh.w = h2u(__float2half2_rn(vx1 * dx1));

        float4 ay;
        ay.x = vy0 * (1.0f - dy0) * inv;  ay.y = vy0 * dy0 * inv;
        ay.z = vy1 * (1.0f - dy1) * inv;  ay.w = vy1 * dy1 * inv;

        s_col[tid] = col;  s_row[tid] = row;
        s_axh[tid] = axh;  s_ay[tid]  = ay;
    }
    __syncthreads();

    // ---------------- Phase 2: gather + stencil ----------------
    const char* __restrict__ featb =
        (const char*)(g_feat_h + (size_t)bidx * FHW * CH + half * CH_HALF) + cg * 8;

    #pragma unroll 1
    for (int b0 = 0; b0 < 32; b0 += 8) {
        const int lb = b0 + bsub;
        if (lb < nb) {
            const int4   row = s_row[lb];          // broadcast LDS.128
            const int4   col = s_col[lb];
            const uint4  axh = s_axh[lb];
            const float4 ay  = s_ay[lb];
            const int   rowv[4] = {row.x, row.y, row.z, row.w};
            const float ayv[4]  = {ay.x, ay.y, ay.z, ay.w};
            const __half2 aw0 = u2h(axh.x), aw1 = u2h(axh.y);
            const __half2 aw2 = u2h(axh.z), aw3 = u2h(axh.w);

            float4 acc = make_float4(0.f, 0.f, 0.f, 0.f);
            #pragma unroll
            for (int r = 0; r < 4; r++) {
                const char* br = featb + rowv[r];
                const uint2 v0 = ldg64cs(br + col.x);
                const uint2 v1 = ldg64cs(br + col.y);
                const uint2 v2 = ldg64cs(br + col.z);
                const uint2 v3 = ldg64cs(br + col.w);

                __half2 rs0 = __hmul2(aw0, u2h(v0.x));
                __half2 rs1 = __hmul2(aw0, u2h(v0.y));
                rs0 = __hfma2(aw1, u2h(v1.x), rs0);
                rs1 = __hfma2(aw1, u2h(v1.y), rs1);
                rs0 = __hfma2(aw2, u2h(v2.x), rs0);
                rs1 = __hfma2(aw2, u2h(v2.y), rs1);
                rs0 = __hfma2(aw3, u2h(v3.x), rs0);
                rs1 = __hfma2(aw3, u2h(v3.y), rs1);

                const float2 lo = __half22float2(rs0);
                const float2 hi = __half22float2(rs1);
                acc.x += ayv[r] * lo.x;
                acc.y += ayv[r] * lo.y;
                acc.z += ayv[r] * hi.x;
                acc.w += ayv[r] * hi.y;
            }

            s_out4[lb * 33 + cg] = acc;   // conflict-free STS.128
        }
    }

    __syncthreads();

    // ---------------- Phase 3: coalesced output store ----------------
    float* o = out + ((size_t)n * CH + (size_t)half * CH_HALF) * NBINS + bin0;
    const float* s_outf = (const float*)s_out4;
    if (bh == 0) store_tile<24>(o, s_outf, tid);
    else         store_tile<25>(o, s_outf, tid);
}

extern "C" void kernel_launch(void* const* d_in, const int* in_sizes, int n_in,
                              void* d_out, int out_size)
{
    const float* bottom_data  = (const float*)d_in[0];  // (2,256,96,96)
    const float* bottom_rois  = (const float*)d_in[1];  // (512,5)
    const float* bottom_trans = (const float*)d_in[2];  // (512,2,7,7)
    float* out = (float*)d_out;                         // (512,256,7,7)

    {
        dim3 tb(32, 8);
        dim3 tg(FHW / 32, CH / 32, BATCH);
        nchw_to_nhwc_half_kernel<<<tg, tb>>>(bottom_data);
    }
    {
        dim3 pg(4, N_ROIS);
        dpsroi_pool_kernel<<<pg, 256>>>(bottom_rois, bottom_trans, out);
    }
}

// round 15
// speedup vs baseline: 1.1334x; 1.1334x over previous
#include <cuda_runtime.h>
#include <cuda_fp16.h>
#include <cuda_bf16.h>

#define BATCH   2
#define CH      256
#define FH      96
#define FW      96
#define FHW     (FH * FW)
#define POOLED  7
#define NBINS   (POOLED * POOLED)
#define N_ROIS  512
#define SPATIAL_SCALE 0.0625f
#define TRANS_STD     0.1f

#define CH_HALF 128
#define ROW_BYTES_H (FW * CH * 2)
#define COL_BYTES_H (CH * 2)

// NHWC fp16 scratch copy of the feature map: 9.4 MB (L2-resident)
__device__ __align__(128) __half g_feat_h[BATCH * FHW * CH];

__device__ __forceinline__ __half2 u2h(unsigned int u) { return *(__half2*)&u; }
__device__ __forceinline__ unsigned int h2u(__half2 h) { return *(unsigned int*)&h; }

// Guaranteed single LDG.64 (ptxas cannot split a v2 asm load).
__device__ __forceinline__ uint2 ldg64cs(const void* p) {
    uint2 v;
    asm("ld.global.nc.v2.u32 {%0, %1}, [%2];" : "=r"(v.x), "=r"(v.y) : "l"(p));
    return v;
}

// ---------------------------------------------------------------------------
// Transpose NCHW f32 -> NHWC f16 via 32x32 shared tiles.
// ---------------------------------------------------------------------------
__global__ __launch_bounds__(256) void nchw_to_nhwc_half_kernel(const float* __restrict__ in) {
    __shared__ float tile[32][33];
    const int b   = blockIdx.z;
    const int hw0 = blockIdx.x * 32;
    const int c0  = blockIdx.y * 32;

    const float* src = in + (size_t)b * CH * FHW;
    #pragma unroll
    for (int j = 0; j < 32; j += 8) {
        tile[threadIdx.y + j][threadIdx.x] =
            src[(size_t)(c0 + threadIdx.y + j) * FHW + hw0 + threadIdx.x];
    }
    __syncthreads();

    const int lane = threadIdx.y * 32 + threadIdx.x;
    const int cp   = lane & 15;
    const int hr   = lane >> 4;
    __half2* dst2 = (__half2*)g_feat_h + (size_t)b * FHW * (CH / 2);
    #pragma unroll
    for (int s = 0; s < 2; s++) {
        const int hl = hr + s * 16;
        const float a  = tile[2 * cp][hl];
        const float bv = tile[2 * cp + 1][hl];
        dst2[(size_t)(hw0 + hl) * (CH / 2) + (c0 >> 1) + cp] = __floats2half2_rn(a, bv);
    }
}

// ---------------------------------------------------------------------------
// Deformable PS-RoI pooling, v15 = v13 body, perfect warp/bin tiling.
// Grid (14, 512): blockIdx.x = half*7 + binGroup. 224 threads = 7 warps.
// Warp w handles bin binGroup*7 + w: exactly one gather per warp, no loop,
// 100% warp-slot activity (49 = 7x7).
// Phase 1: one thread/bin builds {row offs, col offs, half2 x-wts, f32 y-wts}.
// Phase 2: 16 forced LDG.64, HFMA2 column stage, f32 row combine.
// Phase 3: conflict-free [bin][cg] STS.128 staging + grouped store.
// ---------------------------------------------------------------------------

__global__ __launch_bounds__(224, 6) void dpsroi_pool_kernel(
    const float* __restrict__ rois,     // [N_ROIS, 5]
    const float* __restrict__ trans,    // [N_ROIS, 2, 7, 7]
    float* __restrict__ out)            // [N_ROIS, CH, 7, 7]
{
    __shared__ float4 s_out4[7 * 33];         // [bin][33 float4] = 3.7 KB
    __shared__ int4   s_row[7];               // 4 row byte-offsets per bin
    __shared__ int4   s_col[7];               // 4 col byte-offsets per bin
    __shared__ uint4  s_axh[7];               // 4 half2-broadcast x weights
    __shared__ float4 s_ay[7];                // y weights * inv(count)

    const int half = blockIdx.x / 7;          // channel half
    const int grp  = blockIdx.x - half * 7;   // bin group (7 bins)
    const int n    = blockIdx.y;
    const int tid  = threadIdx.x;
    const int cg   = tid & 31;
    const int bsub = tid >> 5;                // warp id = bin within group
    const int bin0 = grp * 7;

    const float* roi = rois + n * 5;
    const int   bidx = (int)roi[0];

    // ---------------- Phase 1: per-bin tables ----------------
    if (tid < 7) {
        const float x1 = rintf(roi[1]) * SPATIAL_SCALE - 0.5f;
        const float y1 = rintf(roi[2]) * SPATIAL_SCALE - 0.5f;
        const float x2 = (rintf(roi[3]) + 1.0f) * SPATIAL_SCALE - 0.5f;
        const float y2 = (rintf(roi[4]) + 1.0f) * SPATIAL_SCALE - 0.5f;
        const float rw = fmaxf(x2 - x1, 0.1f);
        const float rh = fmaxf(y2 - y1, 0.1f);
        const float bin_w = rw * (1.0f / POOLED);
        const float bin_h = rh * (1.0f / POOLED);
        const float sub_w = bin_w * 0.5f;
        const float sub_h = bin_h * 0.5f;

        const int bin = bin0 + tid;
        const int ph = bin / POOLED;
        const int pw = bin - ph * POOLED;

        const float tx = __ldg(trans + (size_t)n * 2 * NBINS + bin) * TRANS_STD;
        const float ty = __ldg(trans + (size_t)n * 2 * NBINS + NBINS + bin) * TRANS_STD;

        const float wstart = (float)pw * bin_w + x1 + tx * rw;
        const float hstart = (float)ph * bin_h + y1 + ty * rh;

        const float w0 = wstart, w1 = wstart + sub_w;
        const float h0 = hstart, h1 = hstart + sub_h;

        const float vx0 = (w0 >= -0.5f && w0 <= (float)FW - 0.5f) ? 1.0f : 0.0f;
        const float vx1 = (w1 >= -0.5f && w1 <= (float)FW - 0.5f) ? 1.0f : 0.0f;
        const float vy0 = (h0 >= -0.5f && h0 <= (float)FH - 0.5f) ? 1.0f : 0.0f;
        const float vy1 = (h1 >= -0.5f && h1 <= (float)FH - 0.5f) ? 1.0f : 0.0f;

        const float wc0 = fminf(fmaxf(w0, 0.0f), (float)FW - 1.0f);
        const float wc1 = fminf(fmaxf(w1, 0.0f), (float)FW - 1.0f);
        const float hc0 = fminf(fmaxf(h0, 0.0f), (float)FH - 1.0f);
        const float hc1 = fminf(fmaxf(h1, 0.0f), (float)FH - 1.0f);

        const float fx0 = floorf(wc0), fx1 = floorf(wc1);
        const float fy0 = floorf(hc0), fy1 = floorf(hc1);
        const float dx0 = wc0 - fx0, dx1 = wc1 - fx1;
        const float dy0 = hc0 - fy0, dy1 = hc1 - fy1;

        int4 col, row;
        col.x = (int)fx0 * COL_BYTES_H;
        col.y = (int)ceilf(wc0) * COL_BYTES_H;
        col.z = (int)fx1 * COL_BYTES_H;
        col.w = (int)ceilf(wc1) * COL_BYTES_H;
        row.x = (int)fy0 * ROW_BYTES_H;
        row.y = (int)ceilf(hc0) * ROW_BYTES_H;
        row.z = (int)fy1 * ROW_BYTES_H;
        row.w = (int)ceilf(hc1) * ROW_BYTES_H;

        const float count = (vx0 + vx1) * (vy0 + vy1);
        const float inv = (count > 0.0f) ? (1.0f / count) : 0.0f;

        uint4 axh;
        axh.x = h2u(__float2half2_rn(vx0 * (1.0f - dx0)));
        axh.y = h2u(__float2half2_rn(vx0 * dx0));
        axh.z = h2u(__float2half2_rn(vx1 * (1.0f - dx1)));
        axh.w = h2u(__float2half2_rn(vx1 * dx1));

        float4 ay;
        ay.x = vy0 * (1.0f - dy0) * inv;  ay.y = vy0 * dy0 * inv;
        ay.z = vy1 * (1.0f - dy1) * inv;  ay.w = vy1 * dy1 * inv;

        s_col[tid] = col;  s_row[tid] = row;
        s_axh[tid] = axh;  s_ay[tid]  = ay;
    }
    __syncthreads();

    // ---------------- Phase 2: one gather per warp (no loop) ----------------
    const char* __restrict__ featb =
        (const char*)(g_feat_h + (size_t)bidx * FHW * CH + half * CH_HALF) + cg * 8;

    {
        const int4   row = s_row[bsub];        // broadcast LDS.128
        const int4   col = s_col[bsub];
        const uint4  axh = s_axh[bsub];
        const float4 ay  = s_ay[bsub];
        const int   rowv[4] = {row.x, row.y, row.z, row.w};
        const float ayv[4]  = {ay.x, ay.y, ay.z, ay.w};
        const __half2 aw0 = u2h(axh.x), aw1 = u2h(axh.y);
        const __half2 aw2 = u2h(axh.z), aw3 = u2h(axh.w);

        float4 acc = make_float4(0.f, 0.f, 0.f, 0.f);
        #pragma unroll
        for (int r = 0; r < 4; r++) {
            const char* br = featb + rowv[r];
            const uint2 v0 = ldg64cs(br + col.x);
            const uint2 v1 = ldg64cs(br + col.y);
            const uint2 v2 = ldg64cs(br + col.z);
            const uint2 v3 = ldg64cs(br + col.w);

            __half2 rs0 = __hmul2(aw0, u2h(v0.x));
            __half2 rs1 = __hmul2(aw0, u2h(v0.y));
            rs0 = __hfma2(aw1, u2h(v1.x), rs0);
            rs1 = __hfma2(aw1, u2h(v1.y), rs1);
            rs0 = __hfma2(aw2, u2h(v2.x), rs0);
            rs1 = __hfma2(aw2, u2h(v2.y), rs1);
            rs0 = __hfma2(aw3, u2h(v3.x), rs0);
            rs1 = __hfma2(aw3, u2h(v3.y), rs1);

            const float2 lo = __half22float2(rs0);
            const float2 hi = __half22float2(rs1);
            acc.x += ayv[r] * lo.x;
            acc.y += ayv[r] * lo.y;
            acc.z += ayv[r] * hi.x;
            acc.w += ayv[r] * hi.y;
        }

        s_out4[bsub * 33 + cg] = acc;   // conflict-free STS.128
    }

    __syncthreads();

    // ---------------- Phase 3: grouped output store ----------------
    // out element (c, bin0+j) <- s_out[j][c];  runs of 7 consecutive floats.
    float* o = out + ((size_t)n * CH + (size_t)half * CH_HALF) * NBINS + bin0;
    const float* s_outf = (const float*)s_out4;
    #pragma unroll
    for (int i = tid; i < CH_HALF * 7; i += 224) {
        const int c = i / 7;
        const int j = i - c * 7;
        o[c * NBINS + j] = s_outf[j * 132 + c];
    }
}

extern "C" void kernel_launch(void* const* d_in, const int* in_sizes, int n_in,
                              void* d_out, int out_size)
{
    const float* bottom_data  = (const float*)d_in[0];  // (2,256,96,96)
    const float* bottom_rois  = (const float*)d_in[1];  // (512,5)
    const float* bottom_trans = (const float*)d_in[2];  // (512,2,7,7)
    float* out = (float*)d_out;                         // (512,256,7,7)

    {
        dim3 tb(32, 8);
        dim3 tg(FHW / 32, CH / 32, BATCH);
        nchw_to_nhwc_half_kernel<<<tg, tb>>>(bottom_data);
    }
    {
        dim3 pg(14, N_ROIS);
        dpsroi_pool_kernel<<<pg, 224>>>(bottom_rois, bottom_trans, out);
    }
}